// round 4
// baseline (speedup 1.0000x reference)
#include <cuda_runtime.h>
#include <math.h>

#define BATCH 8
#define SEQ   1024
#define HID   768
#define INNER 64
#define ENT   9
#define NEGC  1000000000000.0f

// ---------------- scratch (device globals; no allocation allowed) ----------------
__device__ float g_q[BATCH * SEQ * INNER];       // rope'd q, [row][64]
__device__ float g_k[BATCH * SEQ * INNER];       // rope'd k, [row][64]
__device__ float g_be[BATCH * ENT * SEQ];        // bias even (col/n bias)
__device__ float g_bo[BATCH * ENT * SEQ];        // bias odd  (row/m bias)

// =====================================================================
// Fused Kernel A: blocks 0..255 -> proj GEMM (32 rows each) + RoPE
//                 blocks 256..511 -> bias GEMM (32 rows each)
// Dynamic smem 28.7KB = bias layout (proj needs only 10.5KB).
// =====================================================================

__device__ __forceinline__ void proj_body(float* smem,
                                          const float* __restrict__ X,
                                          const float* __restrict__ w1,
                                          const float* __restrict__ b1,
                                          int blk)
{
    float* As = smem;               // [16][36]  (k-major, padded)
    float* Bs = smem + 16 * 36;     // [16][128]

    const int tid = threadIdx.x;
    const int rowBase = blk * 32;

    const bool ldx = tid < 128;
    const int lm = tid >> 2;            // 0..31 (valid when ldx)
    const int lk = (tid & 3) << 2;      // 0,4,8,12
    const float* Xrow = X + (size_t)(rowBase + (lm & 31)) * HID + lk;

    const int nthr = tid & 31;          // pair index i
    const int n0 = nthr << 2;
    const int m0 = (tid >> 5) << 2;     // 0..28

    float acc[4][4];
#pragma unroll
    for (int mi = 0; mi < 4; ++mi)
#pragma unroll
        for (int ni = 0; ni < 4; ++ni) acc[mi][ni] = 0.f;

    const int wi0 = tid, wi1 = tid + 256;
    float4 xa = make_float4(0.f, 0.f, 0.f, 0.f);
    if (ldx) xa = *(const float4*)(Xrow);
    float4 wv0 = *(const float4*)&w1[(wi0 >> 5) * 128 + (wi0 & 31) * 4];
    float4 wv1 = *(const float4*)&w1[(wi1 >> 5) * 128 + (wi1 & 31) * 4];

    for (int kc = 0; kc < HID / 16; ++kc) {
        __syncthreads();
        if (ldx) {
            As[(lk + 0) * 36 + lm] = xa.x;
            As[(lk + 1) * 36 + lm] = xa.y;
            As[(lk + 2) * 36 + lm] = xa.z;
            As[(lk + 3) * 36 + lm] = xa.w;
        }
        *(float4*)&Bs[(wi0 >> 5) * 128 + (wi0 & 31) * 4] = wv0;
        *(float4*)&Bs[(wi1 >> 5) * 128 + (wi1 & 31) * 4] = wv1;
        __syncthreads();

        if (kc + 1 < HID / 16) {
            if (ldx) xa = *(const float4*)(Xrow + (kc + 1) * 16);
            wv0 = *(const float4*)&w1[((kc + 1) * 16 + (wi0 >> 5)) * 128 + (wi0 & 31) * 4];
            wv1 = *(const float4*)&w1[((kc + 1) * 16 + (wi1 >> 5)) * 128 + (wi1 & 31) * 4];
        }

#pragma unroll
        for (int kk = 0; kk < 16; ++kk) {
            float4 av = *(const float4*)(&As[kk * 36 + m0]);
            float4 bv = *(const float4*)(&Bs[kk * 128 + n0]);
            float am[4] = {av.x, av.y, av.z, av.w};
            float bn[4] = {bv.x, bv.y, bv.z, bv.w};
#pragma unroll
            for (int mi = 0; mi < 4; ++mi)
#pragma unroll
                for (int ni = 0; ni < 4; ++ni)
                    acc[mi][ni] = fmaf(am[mi], bn[ni], acc[mi][ni]);
        }
    }

    const int i = nthr;
    const float invf = powf(10000.0f, -(float)i * (1.0f / 32.0f));
    const float4 b1v = *(const float4*)&b1[n0];

#pragma unroll
    for (int mi = 0; mi < 4; ++mi) {
        const int r = rowBase + m0 + mi;
        const int pos = r & (SEQ - 1);
        float sv, cv;
        sincosf((float)pos * invf, &sv, &cv);
        const float q0 = acc[mi][0] + b1v.x;   // proj col 4i   -> q[2i]
        const float k0 = acc[mi][1] + b1v.y;   // proj col 4i+1 -> k[2i]
        const float q1 = acc[mi][2] + b1v.z;   // proj col 4i+2 -> q[2i+1]
        const float k1 = acc[mi][3] + b1v.w;   // proj col 4i+3 -> k[2i+1]
        float2 qo = make_float2(fmaf(q0, cv, -q1 * sv), fmaf(q1, cv, q0 * sv));
        float2 ko = make_float2(fmaf(k0, cv, -k1 * sv), fmaf(k1, cv, k0 * sv));
        ((float2*)g_q)[(r << 5) + i] = qo;
        ((float2*)g_k)[(r << 5) + i] = ko;
    }
}

__device__ __forceinline__ void bias_body(float* smem,
                                          const float* __restrict__ X,
                                          const float* __restrict__ w2,
                                          const float* __restrict__ b2,
                                          int blk)
{
    float* sA = smem;                 // [32][129] X chunk; reused as [256][19] partials
    float* sW = smem + 4864;          // [128][18]

    const int tid = threadIdx.x;
    const int r = tid & 31;
    const int s = tid >> 5;           // k-split 0..7
    const int rowBase = blk * 32;

    float acc[18];
#pragma unroll
    for (int e = 0; e < 18; ++e) acc[e] = 0.f;

    for (int kc = 0; kc < 6; ++kc) {
        __syncthreads();
        for (int i = tid; i < 32 * 32; i += 256) {          // 32 rows x 32 float4
            int rr = i >> 5, j4 = (i & 31) << 2;
            float4 v = *(const float4*)&X[(size_t)(rowBase + rr) * HID + kc * 128 + j4];
            sA[rr * 129 + j4 + 0] = v.x;
            sA[rr * 129 + j4 + 1] = v.y;
            sA[rr * 129 + j4 + 2] = v.z;
            sA[rr * 129 + j4 + 3] = v.w;
        }
        for (int i = tid; i < 128 * 18; i += 256)
            sW[i] = w2[(size_t)(kc * 128) * 18 + i];
        __syncthreads();

        const int kb = s * 16;
#pragma unroll 4
        for (int kk = 0; kk < 16; ++kk) {
            float xv = sA[r * 129 + kb + kk];
            const float* wrow = &sW[(kb + kk) * 18];
#pragma unroll
            for (int e = 0; e < 18; ++e) acc[e] = fmaf(xv, wrow[e], acc[e]);
        }
    }

    __syncthreads();
#pragma unroll
    for (int e = 0; e < 18; ++e) sA[tid * 19 + e] = acc[e];
    __syncthreads();

    for (int i = tid; i < 32 * 18; i += 256) {
        int rr = i / 18, e = i - rr * 18;
        float sum = 0.f;
#pragma unroll
        for (int k = 0; k < 8; ++k) sum += sA[(k * 32 + rr) * 19 + e];
        float val = (sum + b2[e]) * 0.5f;
        int row = rowBase + rr;
        int bb = row >> 10, nn = row & (SEQ - 1);
        int h = e >> 1;
        if ((e & 1) == 0) g_be[(bb * ENT + h) * SEQ + nn] = val;
        else              g_bo[(bb * ENT + h) * SEQ + nn] = val;
    }
}

__global__ __launch_bounds__(256) void k_projbias(const float* __restrict__ X,
                                                  const float* __restrict__ w1,
                                                  const float* __restrict__ b1,
                                                  const float* __restrict__ w2,
                                                  const float* __restrict__ b2)
{
    extern __shared__ __align__(16) float smem[];
    const int bx = blockIdx.x;
    if (bx < 256) proj_body(smem, X, w1, b1, bx);
    else          bias_body(smem, X, w2, b2, bx - 256);
}

// =====================================================================
// Kernel B: out[b,e,m,n] = (qk/8)*mr*mc + (negr*mc + negc + tril) + mr*mc*(be+bo)
// Tile: 128m x 64n, 256 threads, micro-tile 8m x 4n.
// q and k transposed in smem; tile loads mapped m-fast so the transposing STS
// hits consecutive banks (LDG gather is L2-served; g_q/g_k are L2-resident).
// =====================================================================
__global__ __launch_bounds__(256, 3) void k_out(const float* __restrict__ mask,
                                                float* __restrict__ out)
{
    __shared__ __align__(16) float qt[32 * 132];  // [d][m], stride 132
    __shared__ __align__(16) float kt[32 * 68];   // [d][n], stride 68
    __shared__ __align__(16) float bes[ENT * 64];
    __shared__ __align__(16) float bos[ENT * 128];
    __shared__ __align__(16) float mrow[128];
    __shared__ __align__(16) float mcol[64];

    const int tid = threadIdx.x;
    const int nBase = blockIdx.x * 64;
    const int mBase = blockIdx.y * 128;
    const int b = blockIdx.z;
    const int bOff = b * SEQ;

    const int n0 = (tid & 15) << 2;               // 0..60
    const int m0 = (tid >> 4) << 3;               // 0..120

    for (int i = tid; i < ENT * 64; i += 256)
        bes[i] = g_be[(b * ENT + (i >> 6)) * SEQ + nBase + (i & 63)];
    for (int i = tid; i < ENT * 128; i += 256)
        bos[i] = g_bo[(b * ENT + (i >> 7)) * SEQ + mBase + (i & 127)];
    for (int i = tid; i < 128; i += 256) mrow[i] = mask[b * SEQ + mBase + i];
    if (tid < 64) mcol[tid] = mask[b * SEQ + nBase + tid];

    float acc[8][4];
#pragma unroll
    for (int mi = 0; mi < 8; ++mi)
#pragma unroll
        for (int ni = 0; ni < 4; ++ni) acc[mi][ni] = 0.f;

    for (int ch = 0; ch < 2; ++ch) {
        __syncthreads();
        // q tile transposed: m-fast mapping -> conflict-free STS
        for (int i = tid; i < 128 * 8; i += 256) {
            int m = i & 127, d4 = (i >> 7) << 2;
            float4 v = *(const float4*)&g_q[((size_t)(bOff + mBase + m) << 6) + ch * 32 + d4];
            qt[(d4 + 0) * 132 + m] = v.x;
            qt[(d4 + 1) * 132 + m] = v.y;
            qt[(d4 + 2) * 132 + m] = v.z;
            qt[(d4 + 3) * 132 + m] = v.w;
        }
        // k tile transposed: n-fast mapping
        for (int i = tid; i < 64 * 8; i += 256) {
            int n = i & 63, d4 = (i >> 6) << 2;
            float4 v = *(const float4*)&g_k[((size_t)(bOff + nBase + n) << 6) + ch * 32 + d4];
            kt[(d4 + 0) * 68 + n] = v.x;
            kt[(d4 + 1) * 68 + n] = v.y;
            kt[(d4 + 2) * 68 + n] = v.z;
            kt[(d4 + 3) * 68 + n] = v.w;
        }
        __syncthreads();

#pragma unroll 8
        for (int d = 0; d < 32; ++d) {
            float4 kv = *(const float4*)&kt[d * 68 + n0];
            float4 q0 = *(const float4*)&qt[d * 132 + m0];
            float4 q1 = *(const float4*)&qt[d * 132 + m0 + 4];
            float qv[8] = {q0.x, q0.y, q0.z, q0.w, q1.x, q1.y, q1.z, q1.w};
#pragma unroll
            for (int mi = 0; mi < 8; ++mi) {
                acc[mi][0] = fmaf(qv[mi], kv.x, acc[mi][0]);
                acc[mi][1] = fmaf(qv[mi], kv.y, acc[mi][1]);
                acc[mi][2] = fmaf(qv[mi], kv.z, acc[mi][2]);
                acc[mi][3] = fmaf(qv[mi], kv.w, acc[mi][3]);
            }
        }
    }

    // ---- epilogue: fold scale, masks, tril into acc (no mrc table) ----
    float mr[8];
#pragma unroll
    for (int mi = 0; mi < 8; ++mi) mr[mi] = mrow[m0 + mi];
    float4 mcv = *(const float4*)&mcol[n0];
    float mcs[4] = {mcv.x, mcv.y, mcv.z, mcv.w};

#pragma unroll
    for (int mi = 0; mi < 8; ++mi) {
        const float negr = -NEGC * (1.0f - mr[mi]);
        const int m = mBase + m0 + mi;
#pragma unroll
        for (int ni = 0; ni < 4; ++ni) {
            const float mc = mcs[ni];
            const float negc = -NEGC * (1.0f - mc);
            const int n = nBase + n0 + ni;
            const float t = (n < m) ? -NEGC : 0.0f;
            const float p = acc[mi][ni] * 0.125f * mr[mi];
            acc[mi][ni] = fmaf(p, mc, fmaf(negr, mc, negc + t));
        }
    }

    // ---- 9 output planes: o = fmaf(mc, fmaf(mr, be, mr*bo), acc) ----
#pragma unroll
    for (int e = 0; e < ENT; ++e) {
        float4 bev = *(const float4*)&bes[e * 64 + n0];
        float beA[4] = {bev.x, bev.y, bev.z, bev.w};
        const size_t planeRow = (size_t)(b * ENT + e) << 10;
#pragma unroll
        for (int mi = 0; mi < 8; ++mi) {
            const float bo = bos[e * 128 + m0 + mi];
            const float c1 = mr[mi] * bo;
            float4 o;
            o.x = fmaf(mcs[0], fmaf(mr[mi], beA[0], c1), acc[mi][0]);
            o.y = fmaf(mcs[1], fmaf(mr[mi], beA[1], c1), acc[mi][1]);
            o.z = fmaf(mcs[2], fmaf(mr[mi], beA[2], c1), acc[mi][2]);
            o.w = fmaf(mcs[3], fmaf(mr[mi], beA[3], c1), acc[mi][3]);
            *(float4*)&out[((planeRow + mBase + m0 + mi) << 10) + nBase + n0] = o;
        }
    }
}

// =====================================================================
extern "C" void kernel_launch(void* const* d_in, const int* in_sizes, int n_in,
                              void* d_out, int out_size)
{
    const float* X    = (const float*)d_in[0];   // (8,1024,768)
    const float* mask = (const float*)d_in[1];   // (8,1024)
    const float* w1   = (const float*)d_in[2];   // (768,128)
    const float* b1   = (const float*)d_in[3];   // (128,)
    const float* w2   = (const float*)d_in[4];   // (768,18)
    const float* b2   = (const float*)d_in[5];   // (18,)
    float* out = (float*)d_out;                  // (8,9,1024,1024)

    // dynamic smem = bias layout: 4864 (sA/partials) + 2304 (sW) floats
    const int smemBytes = (4864 + 2304) * 4;     // 28672 B
    k_projbias<<<512, 256, smemBytes>>>(X, w1, b1, w2, b2);
    k_out<<<dim3(16, 8, 8), 256>>>(mask, out);
}